// round 6
// baseline (speedup 1.0000x reference)
#include <cuda_runtime.h>
#include <cuda_bf16.h>
#include <math.h>
#include <stdint.h>

#define B_ROWS 8192
#define OBS    128
#define HID    512
#define HEADS  4
#define VSZ    256
#define NU     64
#define TOPK   8
#define NOPT   16

// ---------------- device scratch (static, allocation-free) ----------------
__device__ float g_wbar[HID * VSZ];   // 512x256 head-mean of value_w
__device__ float g_weff[OBS * VSZ];   // 128x256 = pre_fc_w @ wbar
__device__ float g_c0[VSZ];           // pre_fc_b . wbar[:,v] + bbar[v]
__device__ float g_bb[VSZ];           // head-mean of value_b
__device__ float g_A[NOPT];
__device__ float g_C[NOPT];

// ===================== K0: wbar + bbar + per-option scalars ================
// blocks 0..255: 2 rows of wbar each, fully coalesced. block 256: scalars.
__global__ __launch_bounds__(256)
void prep_wbar(const float* __restrict__ value_w,
               const float* __restrict__ value_b,
               const float* __restrict__ p_w,
               const float* __restrict__ p_b) {
    int b = blockIdx.x;
    int t = threadIdx.x;

    if (b == 256) {
        // bbar
        g_bb[t] = 0.25f * (value_b[t] + value_b[VSZ + t] +
                           value_b[2 * VSZ + t] + value_b[3 * VSZ + t]);
        // per-option top-k scalars: 8 warps, 2 options each
        int lane = t & 31, w = t >> 5;
        for (int o = w; o < NOPT; o += 8) {
            float v0 = p_w[o * NU + lane] + p_b[lane];
            float v1 = p_w[o * NU + 32 + lane] + p_b[32 + lane];
            float ssum = 0.f;
#pragma unroll
            for (int it = 0; it < TOPK; it++) {
                float mv; int mi;
                if (v0 >= v1) { mv = v0; mi = lane; } else { mv = v1; mi = lane + 32; }
#pragma unroll
                for (int off = 16; off; off >>= 1) {
                    float ov = __shfl_xor_sync(0xffffffffu, mv, off);
                    int   oi = __shfl_xor_sync(0xffffffffu, mi, off);
                    if (ov > mv || (ov == mv && oi < mi)) { mv = ov; mi = oi; }
                }
                ssum += 1.f / (1.f + expf(-mv));
                if (mi == lane)           v0 = -1e30f;
                else if (mi == lane + 32) v1 = -1e30f;
            }
            if (lane == 0) {
                g_A[o] = ssum * (1.f / 64.f);
                g_C[o] = (8.f - ssum) * (1.f / 64.f);
            }
        }
        return;
    }

#pragma unroll
    for (int rr = 0; rr < 2; rr++) {
        int r = b * 2 + rr;
        const float* p = value_w + (size_t)r * (HEADS * VSZ);
        g_wbar[r * VSZ + t] =
            0.25f * (p[t] + p[VSZ + t] + p[2 * VSZ + t] + p[3 * VSZ + t]);
    }
}

// ===================== K1: W_eff = pre_fc_w @ wbar (+ c0) ==================
// grid (8 vt, 16 rt) = 128 blocks, 256 threads.
// Tile: 8 rows x 32 cols, K chunked by 128 (smem stays ~21 KB, in bounds).
#define BSX 33    // bs column stride: bank(33k+c) = (k+c) mod 32 -> conflict-free
#define PKC 128   // K chunk
__global__ __launch_bounds__(256)
void prep_weff(const float* __restrict__ pfw, const float* __restrict__ pfb) {
    __shared__ float as[8][PKC + 4];   // A rows chunk (broadcast reads)
    __shared__ float bs[PKC * BSX];    // wbar slab chunk [128 k][32 c] stride 33
    __shared__ float red[256];

    int vt = blockIdx.x, rt = blockIdx.y;
    int t = threadIdx.x;
    bool do_c0 = (rt == 0);
    int r = t >> 5, c = t & 31;        // r = warp id (broadcast as-reads)

    float acc = 0.f, s = 0.f;
    for (int kb = 0; kb < HID; kb += PKC) {
        __syncthreads();
        // stage A chunk: 8 rows x 128 k (one float4 per thread)
        {
            int k4 = (t & 31) << 2;
            *(float4*)&as[r][k4] =
                *(const float4*)(pfw + (size_t)(rt * 8 + r) * HID + kb + k4);
        }
        // stage B chunk: 128 k x 32 c (scalar stores, conflict-free)
#pragma unroll
        for (int i = 0; i < 4; i++) {
            int idx = t + i * 256;      // 1024 float4
            int k = idx >> 3, c4 = (idx & 7) << 2;
            float4 v = *(const float4*)(g_wbar + (size_t)(kb + k) * VSZ + vt * 32 + c4);
            bs[k * BSX + c4 + 0] = v.x; bs[k * BSX + c4 + 1] = v.y;
            bs[k * BSX + c4 + 2] = v.z; bs[k * BSX + c4 + 3] = v.w;
        }
        __syncthreads();

#pragma unroll 8
        for (int k4 = 0; k4 < PKC / 4; k4++) {
            float4 a = *(float4*)&as[r][k4 * 4];
            acc += a.x * bs[(k4 * 4 + 0) * BSX + c];
            acc += a.y * bs[(k4 * 4 + 1) * BSX + c];
            acc += a.z * bs[(k4 * 4 + 2) * BSX + c];
            acc += a.w * bs[(k4 * 4 + 3) * BSX + c];
        }
        if (do_c0) {
            // warp r handles local ks [r*16, r*16+16)
#pragma unroll
            for (int i = 0; i < 16; i++) {
                int kl = r * 16 + i;
                s += pfb[kb + kl] * bs[kl * BSX + c];
            }
        }
    }
    g_weff[(size_t)(rt * 8 + r) * VSZ + vt * 32 + c] = acc;

    if (do_c0) {
        red[t] = s;
        __syncthreads();
        if (t < 32) {
            float ss = 0.f;
#pragma unroll
            for (int m = 0; m < 8; m++) ss += red[t + 32 * m];
            g_c0[vt * 32 + t] = ss + g_bb[vt * 32 + t];
        }
    }
}

// ===================== K2: main GEMM ======================================
// out[b,v] = A[opt_b] * (x_b . W_eff[:,v] + c0[v]) + C[opt_b] * bb[v]
// 256 blocks x 256 threads, tile 32 rows x 256 cols, K chunked by 64.
// Thread: 1 row x 32 interleaved cols (tq*4 + 32j) -> 1-cycle LDS wavefronts.
#define KX  132   // xs row stride
#define WSK 64    // k chunk

#define FMA2(acc, a, b) \
    asm("fma.rn.f32x2 %0, %1, %2, %0;" : "+l"(acc) : "l"(a), "l"(b))

__global__ __launch_bounds__(256, 2)
void main_gemm(const float* __restrict__ x, const int* __restrict__ opt,
               float* __restrict__ out) {
    extern __shared__ float sm[];
    float* ws  = sm;                    // 64 k x 256 v
    float* xs  = ws + WSK * VSZ;        // 32 rows x KX
    float* sA  = xs + 32 * KX;          // 32
    float* sC  = sA + 32;               // 32
    float* sc0 = sC + 32;               // 256
    float* sbb = sc0 + VSZ;             // 256

    int t  = threadIdx.x;
    int rb = blockIdx.x * 32;
    int tq = t & 7, row = t >> 3;

    // stage x tile (full K=128)
#pragma unroll
    for (int i = 0; i < 4; i++) {
        int idx = t + i * 256;          // 1024 float4
        int r = idx >> 5, k4 = (idx & 31) << 2;
        *(float4*)&xs[r * KX + k4] = *(const float4*)(x + (size_t)(rb + r) * OBS + k4);
    }
    if (t < 32) {
        int o = opt[rb + t];
        sA[t] = g_A[o];
        sC[t] = g_C[o];
    }
    sc0[t] = g_c0[t];
    sbb[t] = g_bb[t];

    unsigned long long acc[8][2];
#pragma unroll
    for (int j = 0; j < 8; j++) { acc[j][0] = 0ull; acc[j][1] = 0ull; }

    for (int kb = 0; kb < OBS; kb += WSK) {
        __syncthreads();
        // stage W_eff chunk [64 k x 256 v]
#pragma unroll
        for (int i = 0; i < 16; i++) {
            int idx = t + i * 256;      // 4096 float4
            *(float4*)&ws[idx * 4] =
                *(const float4*)(g_weff + (size_t)kb * VSZ + idx * 4);
        }
        __syncthreads();

#pragma unroll 4
        for (int k4 = 0; k4 < WSK / 4; k4++) {
            float4 a4 = *(float4*)&xs[row * KX + kb + k4 * 4];
#pragma unroll
            for (int kk = 0; kk < 4; kk++) {
                float a = (&a4.x)[kk];
                unsigned long long aa;
                asm("mov.b64 %0, {%1, %1};" : "=l"(aa) : "r"(__float_as_uint(a)));
                const float* wrow = &ws[(k4 * 4 + kk) * VSZ + tq * 4];
#pragma unroll
                for (int j = 0; j < 8; j++) {
                    ulonglong2 w = *(const ulonglong2*)(wrow + 32 * j);
                    FMA2(acc[j][0], aa, w.x);
                    FMA2(acc[j][1], aa, w.y);
                }
            }
        }
    }

    // epilogue
    float Ar = sA[row], Cr = sC[row];
    float* orow = out + (size_t)(rb + row) * VSZ;
#pragma unroll
    for (int j = 0; j < 8; j++) {
        int c = tq * 4 + 32 * j;
        unsigned int u0, u1, u2, u3;
        asm("mov.b64 {%0,%1}, %2;" : "=r"(u0), "=r"(u1) : "l"(acc[j][0]));
        asm("mov.b64 {%0,%1}, %2;" : "=r"(u2), "=r"(u3) : "l"(acc[j][1]));
        float4 o4;
        o4.x = Ar * (__uint_as_float(u0) + sc0[c + 0]) + Cr * sbb[c + 0];
        o4.y = Ar * (__uint_as_float(u1) + sc0[c + 1]) + Cr * sbb[c + 1];
        o4.z = Ar * (__uint_as_float(u2) + sc0[c + 2]) + Cr * sbb[c + 2];
        o4.w = Ar * (__uint_as_float(u3) + sc0[c + 3]) + Cr * sbb[c + 3];
        *(float4*)(orow + c) = o4;
    }
}

// ---------------- launch ---------------------------------------------------
extern "C" void kernel_launch(void* const* d_in, const int* in_sizes, int n_in,
                              void* d_out, int out_size) {
    (void)in_sizes; (void)n_in; (void)out_size;
    const float* x        = (const float*)d_in[0];
    const int*   option   = (const int*)  d_in[1];
    const float* pre_fc_w = (const float*)d_in[2];
    const float* pre_fc_b = (const float*)d_in[3];
    const float* value_w  = (const float*)d_in[4];
    const float* value_b  = (const float*)d_in[5];
    const float* p_w      = (const float*)d_in[6];
    const float* p_b      = (const float*)d_in[7];
    float* out = (float*)d_out;

    prep_wbar<<<257, 256>>>(value_w, value_b, p_w, p_b);
    prep_weff<<<dim3(8, 16), 256>>>(pre_fc_w, pre_fc_b);

    size_t smem = (WSK * VSZ + 32 * KX + 32 + 32 + VSZ + VSZ) * sizeof(float);
    cudaFuncSetAttribute(main_gemm, cudaFuncAttributeMaxDynamicSharedMemorySize, (int)smem);
    main_gemm<<<256, 256, smem>>>(x, option, out);
}

// round 7
// speedup vs baseline: 1.7260x; 1.7260x over previous
#include <cuda_runtime.h>
#include <cuda_bf16.h>
#include <math.h>
#include <stdint.h>

#define B_ROWS 8192
#define OBS    128
#define HID    512
#define HEADS  4
#define VSZ    256
#define NU     64
#define TOPK   8
#define NOPT   16

// ---------------- device scratch (static, allocation-free) ----------------
__device__ float g_weff[OBS * VSZ];   // 128x256 = pre_fc_w @ wbar
__device__ float g_c0[VSZ];           // pre_fc_b . wbar[:,v] + bbar[v]
__device__ float g_bb[VSZ];           // head-mean of value_b
__device__ float g_A[NOPT];
__device__ float g_C[NOPT];

// ===================== K1: fused prep ======================================
// grid (8 vt, 17): rt 0..15 compute W_eff (8 rows x 32 cols, K=512 chunked);
// rt==0 additionally computes bbar + c0 for its 32 cols.
// block (vt==0, rt==16) computes per-option top-k scalars; other rt==16 exit.
// wbar is never materialized: bs staging head-means value_w on the fly.
#define BSX 33    // bank(33k+c) = (k+c) mod 32 -> conflict-free
#define PKC 128   // K chunk
__global__ __launch_bounds__(256)
void prep_all(const float* __restrict__ value_w,
              const float* __restrict__ value_b,
              const float* __restrict__ pfw,
              const float* __restrict__ pfb,
              const float* __restrict__ p_w,
              const float* __restrict__ p_b) {
    int vt = blockIdx.x, rt = blockIdx.y;
    int t = threadIdx.x;

    if (rt == 16) {
        if (vt != 0) return;
        // ---- per-option top-k scalars: 8 warps, 2 options each ----
        int lane = t & 31, w = t >> 5;
        for (int o = w; o < NOPT; o += 8) {
            float v0 = p_w[o * NU + lane] + p_b[lane];
            float v1 = p_w[o * NU + 32 + lane] + p_b[32 + lane];
            float ssum = 0.f;
#pragma unroll
            for (int it = 0; it < TOPK; it++) {
                float mv; int mi;
                if (v0 >= v1) { mv = v0; mi = lane; } else { mv = v1; mi = lane + 32; }
#pragma unroll
                for (int off = 16; off; off >>= 1) {
                    float ov = __shfl_xor_sync(0xffffffffu, mv, off);
                    int   oi = __shfl_xor_sync(0xffffffffu, mi, off);
                    if (ov > mv || (ov == mv && oi < mi)) { mv = ov; mi = oi; }
                }
                ssum += 1.f / (1.f + expf(-mv));
                if (mi == lane)           v0 = -1e30f;
                else if (mi == lane + 32) v1 = -1e30f;
            }
            if (lane == 0) {
                g_A[o] = ssum * (1.f / 64.f);
                g_C[o] = (8.f - ssum) * (1.f / 64.f);
            }
        }
        return;
    }

    __shared__ float as[8][PKC + 4];   // pre_fc_w rows chunk (broadcast reads)
    __shared__ float bs[PKC * BSX];    // wbar slab chunk [128 k][32 c]
    __shared__ float red[256];

    bool do_c0 = (rt == 0);
    int r = t >> 5, c = t & 31;        // r = warp id

    float acc = 0.f, s = 0.f;
    for (int kb = 0; kb < HID; kb += PKC) {
        __syncthreads();
        // stage A chunk: 8 rows x 128 k (one float4 per thread)
        {
            int k4 = (t & 31) << 2;
            *(float4*)&as[r][k4] =
                *(const float4*)(pfw + (size_t)(rt * 8 + r) * HID + kb + k4);
        }
        // stage B chunk with on-the-fly head mean of value_w
#pragma unroll
        for (int i = 0; i < 4; i++) {
            int idx = t + i * 256;      // 1024 float4
            int k = idx >> 3, c4 = (idx & 7) << 2;
            const float* p = value_w + (size_t)(kb + k) * (HEADS * VSZ) + vt * 32 + c4;
            float4 h0 = *(const float4*)(p);
            float4 h1 = *(const float4*)(p + VSZ);
            float4 h2 = *(const float4*)(p + 2 * VSZ);
            float4 h3 = *(const float4*)(p + 3 * VSZ);
            bs[k * BSX + c4 + 0] = 0.25f * (h0.x + h1.x + h2.x + h3.x);
            bs[k * BSX + c4 + 1] = 0.25f * (h0.y + h1.y + h2.y + h3.y);
            bs[k * BSX + c4 + 2] = 0.25f * (h0.z + h1.z + h2.z + h3.z);
            bs[k * BSX + c4 + 3] = 0.25f * (h0.w + h1.w + h2.w + h3.w);
        }
        __syncthreads();

#pragma unroll 8
        for (int k4 = 0; k4 < PKC / 4; k4++) {
            float4 a = *(float4*)&as[r][k4 * 4];
            acc += a.x * bs[(k4 * 4 + 0) * BSX + c];
            acc += a.y * bs[(k4 * 4 + 1) * BSX + c];
            acc += a.z * bs[(k4 * 4 + 2) * BSX + c];
            acc += a.w * bs[(k4 * 4 + 3) * BSX + c];
        }
        if (do_c0) {
            // warp r handles local ks [r*16, r*16+16)
#pragma unroll
            for (int i = 0; i < 16; i++) {
                int kl = r * 16 + i;
                s += pfb[kb + kl] * bs[kl * BSX + c];
            }
        }
    }
    g_weff[(size_t)(rt * 8 + r) * VSZ + vt * 32 + c] = acc;

    if (do_c0) {
        red[t] = s;
        __syncthreads();
        if (t < 32) {
            float ss = 0.f;
#pragma unroll
            for (int m = 0; m < 8; m++) ss += red[t + 32 * m];
            int col = vt * 32 + t;
            float bb = 0.25f * (value_b[col] + value_b[VSZ + col] +
                                value_b[2 * VSZ + col] + value_b[3 * VSZ + col]);
            g_bb[col] = bb;
            g_c0[col] = ss + bb;
        }
    }
}

// ===================== K2: main GEMM ======================================
// out[b,v] = A[opt_b] * (x_b . W_eff[:,v] + c0[v]) + C[opt_b] * bb[v]
// 128 blocks x 512 threads; tile 64 rows x 256 cols, K chunked by 64.
// Thread: 8 rows x 4 cols. Per warp per k: 1 LDS.128 (W, no conflict) +
// amortized broadcast x loads + 16 FFMA2 -> FMA-pipe-bound.
#define KX  132   // xs row stride
#define WSK 64    // k chunk

#define FMA2(acc, a, b) \
    asm("fma.rn.f32x2 %0, %1, %2, %0;" : "+l"(acc) : "l"(a), "l"(b))

__global__ __launch_bounds__(512)
void main_gemm(const float* __restrict__ x, const int* __restrict__ opt,
               float* __restrict__ out) {
    extern __shared__ float sm[];
    float* ws  = sm;                    // 64 k x 256 v
    float* xs  = ws + WSK * VSZ;        // 64 rows x KX
    float* sA  = xs + 64 * KX;          // 64
    float* sC  = sA + 64;               // 64
    float* sc0 = sC + 64;               // 256
    float* sbb = sc0 + VSZ;             // 256

    int t  = threadIdx.x;
    int rb = blockIdx.x * 64;
    int rg = t >> 6;                    // 8 row-groups of 8 rows (uniform per warp)
    int cg = t & 63;                    // 64 col-groups of 4 cols

    // stage x tile (full K=128): 2048 float4
#pragma unroll
    for (int i = 0; i < 4; i++) {
        int idx = t + i * 512;
        int r = idx >> 5, k4 = (idx & 31) << 2;
        *(float4*)&xs[r * KX + k4] = *(const float4*)(x + (size_t)(rb + r) * OBS + k4);
    }
    if (t < 64) {
        int o = opt[rb + t];
        sA[t] = g_A[o];
        sC[t] = g_C[o];
    }
    if (t < 256) {
        sc0[t] = g_c0[t];
        sbb[t] = g_bb[t];
    }

    unsigned long long acc[8][2];       // 8 rows x 4 cols (2 packed f32x2 per row)
#pragma unroll
    for (int i = 0; i < 8; i++) { acc[i][0] = 0ull; acc[i][1] = 0ull; }

    for (int kb = 0; kb < OBS; kb += WSK) {
        __syncthreads();
        // stage W_eff chunk [64 k x 256 v]: 4096 float4
#pragma unroll
        for (int i = 0; i < 8; i++) {
            int idx = t + i * 512;
            *(float4*)&ws[idx * 4] =
                *(const float4*)(g_weff + (size_t)kb * VSZ + idx * 4);
        }
        __syncthreads();

#pragma unroll 2
        for (int k4 = 0; k4 < WSK / 4; k4++) {
            // broadcast x: 8 rows x 4 k in registers
            float4 a8[8];
#pragma unroll
            for (int i = 0; i < 8; i++)
                a8[i] = *(float4*)&xs[(rg * 8 + i) * KX + kb + k4 * 4];
#pragma unroll
            for (int kk = 0; kk < 4; kk++) {
                ulonglong2 w = *(const ulonglong2*)&ws[(k4 * 4 + kk) * VSZ + cg * 4];
#pragma unroll
                for (int i = 0; i < 8; i++) {
                    float a = (&a8[i].x)[kk];
                    unsigned long long aa;
                    asm("mov.b64 %0, {%1, %1};" : "=l"(aa) : "r"(__float_as_uint(a)));
                    FMA2(acc[i][0], aa, w.x);
                    FMA2(acc[i][1], aa, w.y);
                }
            }
        }
    }

    // epilogue
#pragma unroll
    for (int i = 0; i < 8; i++) {
        int rl  = rg * 8 + i;
        float Ar = sA[rl], Cr = sC[rl];
        int c = cg * 4;
        unsigned int u0, u1, u2, u3;
        asm("mov.b64 {%0,%1}, %2;" : "=r"(u0), "=r"(u1) : "l"(acc[i][0]));
        asm("mov.b64 {%0,%1}, %2;" : "=r"(u2), "=r"(u3) : "l"(acc[i][1]));
        float4 o4;
        o4.x = Ar * (__uint_as_float(u0) + sc0[c + 0]) + Cr * sbb[c + 0];
        o4.y = Ar * (__uint_as_float(u1) + sc0[c + 1]) + Cr * sbb[c + 1];
        o4.z = Ar * (__uint_as_float(u2) + sc0[c + 2]) + Cr * sbb[c + 2];
        o4.w = Ar * (__uint_as_float(u3) + sc0[c + 3]) + Cr * sbb[c + 3];
        *(float4*)(out + (size_t)(rb + rl) * VSZ + c) = o4;
    }
}

// ---------------- launch ---------------------------------------------------
extern "C" void kernel_launch(void* const* d_in, const int* in_sizes, int n_in,
                              void* d_out, int out_size) {
    (void)in_sizes; (void)n_in; (void)out_size;
    const float* x        = (const float*)d_in[0];
    const int*   option   = (const int*)  d_in[1];
    const float* pre_fc_w = (const float*)d_in[2];
    const float* pre_fc_b = (const float*)d_in[3];
    const float* value_w  = (const float*)d_in[4];
    const float* value_b  = (const float*)d_in[5];
    const float* p_w      = (const float*)d_in[6];
    const float* p_b      = (const float*)d_in[7];
    float* out = (float*)d_out;

    prep_all<<<dim3(8, 17), 256>>>(value_w, value_b, pre_fc_w, pre_fc_b, p_w, p_b);

    size_t smem = (WSK * VSZ + 64 * KX + 64 + 64 + VSZ + VSZ) * sizeof(float);
    cudaFuncSetAttribute(main_gemm, cudaFuncAttributeMaxDynamicSharedMemorySize, (int)smem);
    main_gemm<<<128, 512, smem>>>(x, option, out);
}